// round 6
// baseline (speedup 1.0000x reference)
#include <cuda_runtime.h>
#include <cuda_bf16.h>
#include <cuda_fp16.h>
#include <math.h>
#include <cstdint>

// Problem constants (fixed by setup_inputs)
#define V_N   20000
#define VPAD  20096          // 157 * 128 (multiple of 64 too)
#define D_K   256
#define NHEAD 4
#define O_DIM 128
#define KCAT  1024           // NHEAD * D_K  (GEMM K)
#define KNBR  16

// ---------------- scratch (no allocations allowed) ----------------
__device__ __half   g_xh[(size_t)VPAD * D_K];          // x fp16 [v][d], 10.3 MB
__device__ float    g_attn[NHEAD * V_N];
__device__ float    g_wa[NHEAD * D_K];
__device__ float    g_bbar[O_DIM];
__device__ uint32_t g_Yh[(size_t)VPAD * (KCAT / 2)];   // Y bf16 hi [v][h*128+d/2], 41 MB
__device__ uint32_t g_Yl[(size_t)VPAD * (KCAT / 2)];   // lo residual, 41 MB
__device__ uint32_t g_WBh[O_DIM * (KCAT / 2)];         // Wcat [n=o][k=h*256+d] bf16 hi
__device__ uint32_t g_WBl[O_DIM * (KCAT / 2)];         // lo residual
__device__ int      g_adj64;

// ======================= helpers =======================
__device__ __forceinline__ uint32_t smem_u32(const void* p) {
    uint32_t a;
    asm("{ .reg .u64 t; cvta.to.shared.u64 t, %1; cvt.u32.u64 %0, t; }" : "=r"(a) : "l"(p));
    return a;
}
#define SW128(off) ((off) ^ (((off) >> 3) & 0x70))

#define LDSM4(r, addr) \
    asm volatile("ldmatrix.sync.aligned.m8n8.x4.shared.b16 {%0,%1,%2,%3}, [%4];" \
        : "=r"((r)[0]), "=r"((r)[1]), "=r"((r)[2]), "=r"((r)[3]) : "r"(addr))

#define MMA16(c, a, b) \
    asm volatile("mma.sync.aligned.m16n8k16.row.col.f32.bf16.bf16.f32 " \
        "{%0,%1,%2,%3}, {%4,%5,%6,%7}, {%8,%9}, {%0,%1,%2,%3};" \
        : "+f"((c)[0]), "+f"((c)[1]), "+f"((c)[2]), "+f"((c)[3]) \
        : "r"((a)[0]), "r"((a)[1]), "r"((a)[2]), "r"((a)[3]), "r"((b)[0]), "r"((b)[1]))

#define CP_ASYNC16(dst, src) \
    asm volatile("cp.async.cg.shared.global [%0], [%1], 16;" :: "r"(dst), "l"(src))

__device__ __forceinline__ uint32_t bf16_pack_hi(float a, float b, float& ra, float& rb) {
    __nv_bfloat162 h = __floats2bfloat162_rn(a, b);
    ra = a - __bfloat162float(h.x);
    rb = b - __bfloat162float(h.y);
    return *(uint32_t*)&h;
}
__device__ __forceinline__ uint32_t bf16_pack(float a, float b) {
    __nv_bfloat162 h = __floats2bfloat162_rn(a, b);
    return *(uint32_t*)&h;
}

// ---------------- adj dtype detection ----------------
__global__ void detect_adj_kernel(const void* __restrict__ adj) {
    const long long* p = (const long long*)adj;
    int ok = 1;
    for (int i = 0; i < 64; i++) {
        long long v = p[i];
        if (v < 0 || v > (long long)V_N) { ok = 0; break; }
    }
    g_adj64 = ok;
}

// ---------------- wa[h,d] = sum_o W[h,d,o]*a[h,o]; bbar ----------------
__global__ void wa_kernel(const float* __restrict__ W, const float* __restrict__ a,
                          const float* __restrict__ b) {
    int h = blockIdx.x;
    int d = threadIdx.x;
    const float* Wd = W + ((size_t)h * D_K + d) * O_DIM;
    const float* ah = a + h * O_DIM;
    float s = 0.f;
    #pragma unroll 8
    for (int o = 0; o < O_DIM; o++) s += Wd[o] * ah[o];
    g_wa[h * D_K + d] = s;
    if (h == 0 && d < O_DIM)
        g_bbar[d] = 0.25f * (b[d] + b[O_DIM + d] + b[2 * O_DIM + d] + b[3 * O_DIM + d]);
}

// ---------------- B repack: Wcat[n=o][k=h*256+d] -> bf16 hi/lo ----------------
__global__ void bprep_kernel(const float* __restrict__ W) {
    int o = blockIdx.x;             // 0..127
    int q = threadIdx.x;            // 0..511 -> k pair (2q, 2q+1)
    int k = 2 * q;
    int h = k >> 8, d = k & 255;
    float w0 = W[((size_t)h * D_K + d)     * O_DIM + o];
    float w1 = W[((size_t)h * D_K + d + 1) * O_DIM + o];
    float r0, r1;
    uint32_t hi = bf16_pack_hi(w0, w1, r0, r1);
    g_WBh[o * (KCAT / 2) + q] = hi;
    g_WBl[o * (KCAT / 2) + q] = bf16_pack(r0, r1);
}

// ---------------- x prep: fp16 convert + fused attn dots ----------------
__global__ __launch_bounds__(256) void prepx_kernel(const float* __restrict__ x) {
    __shared__ float swa[NHEAD * D_K];
    int tid = threadIdx.x;
    for (int i = tid; i < NHEAD * D_K; i += 256) swa[i] = g_wa[i];
    __syncthreads();

    int wid = tid >> 5, lane = tid & 31;
    int v  = blockIdx.x * 8 + wid;
    int d0 = lane * 8;

    float4 v0 = make_float4(0.f, 0.f, 0.f, 0.f), v1 = v0;
    if (v < V_N) {
        const float* xp = x + (size_t)v * D_K + d0;
        v0 = *(const float4*)xp;
        v1 = *(const float4*)(xp + 4);
    }
    float f[8] = {v0.x, v0.y, v0.z, v0.w, v1.x, v1.y, v1.z, v1.w};
    __half2 p0 = __float22half2_rn(make_float2(f[0], f[1]));
    __half2 p1 = __float22half2_rn(make_float2(f[2], f[3]));
    __half2 p2 = __float22half2_rn(make_float2(f[4], f[5]));
    __half2 p3 = __float22half2_rn(make_float2(f[6], f[7]));
    ((uint4*)g_xh)[(size_t)v * 32 + lane] =
        make_uint4(*(uint32_t*)&p0, *(uint32_t*)&p1, *(uint32_t*)&p2, *(uint32_t*)&p3);

    #pragma unroll
    for (int h = 0; h < NHEAD; h++) {
        const float* wah = swa + h * D_K + d0;
        float s = 0.f;
        #pragma unroll
        for (int j = 0; j < 8; j++) s += f[j] * wah[j];
        #pragma unroll
        for (int off = 16; off; off >>= 1) s += __shfl_xor_sync(0xffffffffu, s, off);
        if (lane == 0 && v < V_N) g_attn[h * V_N + v] = s;
    }
}

// ---------------- gather: softmax coefs + x-space aggregation -> Y bf16 hi/lo ----------------
// 2 nodes per 256-thread block; 128 threads per node, thread owns d-pair.
__global__ __launch_bounds__(256) void gather_kernel(const void* __restrict__ adj) {
    int local = threadIdx.x >> 7;
    int t     = threadIdx.x & 127;
    int v     = blockIdx.x * 2 + local;

    __shared__ float s_coef[2][NHEAD * KNBR];
    __shared__ int   s_idx [2][KNBR];

    if (t < 64) {
        int k = t & 15;
        int h = t >> 4;
        long long a;
        if (g_adj64) a = ((const long long*)adj)[(size_t)v * KNBR + k];
        else         a = (long long)((const int*)adj)[(size_t)v * KNBR + k];
        bool pad = (a >= (long long)V_N) || (a < 0);
        int n = pad ? 0 : (int)a;
        float sc = pad ? -1e9f : g_attn[h * V_N + n];

        float mx = sc;
        #pragma unroll
        for (int off = 8; off; off >>= 1)
            mx = fmaxf(mx, __shfl_xor_sync(0xffffffffu, mx, off));
        float e = __expf(sc - mx);
        float sum = e;
        #pragma unroll
        for (int off = 8; off; off >>= 1)
            sum += __shfl_xor_sync(0xffffffffu, sum, off);
        s_coef[local][t] = pad ? 0.f : (e / sum);
        if (h == 0) s_idx[local][k] = n;
    }
    __syncthreads();

    const __half2* xh2 = (const __half2*)g_xh;
    float2 acc[NHEAD];
    #pragma unroll
    for (int h = 0; h < NHEAD; h++) acc[h] = make_float2(0.f, 0.f);

    const float* cf = s_coef[local];
    const int*   ix = s_idx [local];
    #pragma unroll
    for (int k = 0; k < KNBR; k++) {
        int n = ix[k];
        float2 fv = __half22float2(__ldg(xh2 + (size_t)n * 128 + t));
        #pragma unroll
        for (int h = 0; h < NHEAD; h++) {
            float c = cf[h * KNBR + k];
            acc[h].x = fmaf(c, fv.x, acc[h].x);
            acc[h].y = fmaf(c, fv.y, acc[h].y);
        }
    }
    // write Y hi/lo: k-pair index = h*128 + t
    #pragma unroll
    for (int h = 0; h < NHEAD; h++) {
        float r0, r1;
        uint32_t hi = bf16_pack_hi(acc[h].x, acc[h].y, r0, r1);
        size_t idx = (size_t)v * (KCAT / 2) + h * 128 + t;
        g_Yh[idx] = hi;
        g_Yl[idx] = bf16_pack(r0, r1);
    }
}

// ---------------- GEMM: out = relu(0.25 * Y @ Wcat^T + bbar) ----------------
// [VPAD, 1024] x [1024, 128]; BM=64, BN=64, KC=64, 128 threads, 2-stage cp.async.
#define GM 64
#define GN 64
#define KC 64
#define NCHUNK (KCAT / KC)   // 16
#define BUFSZ  32768
#define SOA_H  0
#define SOA_L  8192
#define SOB_H  16384
#define SOB_L  24576
#define SMEM_SZ (2 * BUFSZ)  // 65536

__device__ __forceinline__ void load_chunk(uint32_t sb, int buf, int kc,
                                           int m0, int n0, int tid) {
    uint32_t base = sb + buf * BUFSZ;
    #pragma unroll
    for (int i = 0; i < 4; i++) {
        int idx = tid + i * 128;       // 512 (row,seg) pairs
        int row = idx >> 3, seg = idx & 7;
        uint32_t sw = SW128((uint32_t)(row * 128 + seg * 16));
        size_t   ao = (size_t)(m0 + row) * 128 + kc * 8 + seg;   // uint4 units
        size_t   bo = (size_t)(n0 + row) * 128 + kc * 8 + seg;
        CP_ASYNC16(base + SOA_H + sw, (const uint4*)g_Yh  + ao);
        CP_ASYNC16(base + SOA_L + sw, (const uint4*)g_Yl  + ao);
        CP_ASYNC16(base + SOB_H + sw, (const uint4*)g_WBh + bo);
        CP_ASYNC16(base + SOB_L + sw, (const uint4*)g_WBl + bo);
    }
    asm volatile("cp.async.commit_group;" ::: "memory");
}

__global__ __launch_bounds__(128) void gemm_mma_kernel(float* __restrict__ out) {
    extern __shared__ char smem[];
    uint32_t sb = smem_u32(smem);
    int tid = threadIdx.x, wid = tid >> 5, lane = tid & 31;
    int m0 = blockIdx.x * GM, n0 = blockIdx.y * GN;
    int wm = (wid & 1) * 32, wn = (wid >> 1) * 32;

    float acc[2][4][4];
    #pragma unroll
    for (int i = 0; i < 2; i++)
        #pragma unroll
        for (int j = 0; j < 4; j++)
            #pragma unroll
            for (int q = 0; q < 4; q++) acc[i][j][q] = 0.f;

    int lrA = lane & 15;
    int hA  = lane >> 4;
    int lrB = (lane & 7) + ((lane >> 4) << 3);
    int hB  = (lane >> 3) & 1;

    load_chunk(sb, 0, 0, m0, n0, tid);

    for (int kc = 0; kc < NCHUNK; kc++) {
        if (kc + 1 < NCHUNK) {
            load_chunk(sb, (kc + 1) & 1, kc + 1, m0, n0, tid);
            asm volatile("cp.async.wait_group 1;" ::: "memory");
        } else {
            asm volatile("cp.async.wait_group 0;" ::: "memory");
        }
        __syncthreads();

        uint32_t base = sb + (kc & 1) * BUFSZ;
        #pragma unroll
        for (int ks = 0; ks < 4; ks++) {
            uint32_t a_h[2][4], a_l[2][4];
            #pragma unroll
            for (int mt = 0; mt < 2; mt++) {
                uint32_t off = SW128((uint32_t)((wm + mt * 16 + lrA) * 128 + ks * 32 + hA * 16));
                LDSM4(a_h[mt], base + SOA_H + off);
                LDSM4(a_l[mt], base + SOA_L + off);
            }
            #pragma unroll
            for (int p = 0; p < 2; p++) {
                uint32_t bh[4], bl[4];
                uint32_t off = SW128((uint32_t)((wn + p * 16 + lrB) * 128 + ks * 32 + hB * 16));
                LDSM4(bh, base + SOB_H + off);
                LDSM4(bl, base + SOB_L + off);
                #pragma unroll
                for (int mt = 0; mt < 2; mt++) {
                    MMA16(acc[mt][2 * p],     a_h[mt], &bh[0]);
                    MMA16(acc[mt][2 * p],     a_h[mt], &bl[0]);
                    MMA16(acc[mt][2 * p],     a_l[mt], &bh[0]);
                    MMA16(acc[mt][2 * p + 1], a_h[mt], &bh[2]);
                    MMA16(acc[mt][2 * p + 1], a_h[mt], &bl[2]);
                    MMA16(acc[mt][2 * p + 1], a_l[mt], &bh[2]);
                }
            }
        }
        __syncthreads();
    }

    // epilogue: out = relu(0.25*acc + bbar), guarded rows
    int g  = lane >> 2;
    int t2 = (lane & 3) * 2;
    #pragma unroll
    for (int mt = 0; mt < 2; mt++) {
        int r0 = m0 + wm + mt * 16 + g;
        #pragma unroll
        for (int nt = 0; nt < 4; nt++) {
            int c = n0 + wn + nt * 8 + t2;
            float bx = g_bbar[c], by = g_bbar[c + 1];
            if (r0 < V_N) {
                float rx = fmaxf(fmaf(acc[mt][nt][0], 0.25f, bx), 0.f);
                float ry = fmaxf(fmaf(acc[mt][nt][1], 0.25f, by), 0.f);
                *(float2*)(out + (size_t)r0 * O_DIM + c) = make_float2(rx, ry);
            }
            if (r0 + 8 < V_N) {
                float rx = fmaxf(fmaf(acc[mt][nt][2], 0.25f, bx), 0.f);
                float ry = fmaxf(fmaf(acc[mt][nt][3], 0.25f, by), 0.f);
                *(float2*)(out + (size_t)(r0 + 8) * O_DIM + c) = make_float2(rx, ry);
            }
        }
    }
}

// ---------------- launch ----------------
extern "C" void kernel_launch(void* const* d_in, const int* in_sizes, int n_in,
                              void* d_out, int out_size) {
    const float* x   = (const float*)d_in[0];   // [V, D]
    const float* W   = (const float*)d_in[1];   // [H, D, O]
    const float* a   = (const float*)d_in[2];   // [H, O]
    const float* b   = (const float*)d_in[3];   // [H, O]
    const void*  adj = d_in[4];                 // [V, K] int32 or int64
    float* out = (float*)d_out;                 // [V, O]

    cudaFuncSetAttribute(gemm_mma_kernel, cudaFuncAttributeMaxDynamicSharedMemorySize, SMEM_SZ);

    detect_adj_kernel<<<1, 1>>>(adj);
    wa_kernel<<<NHEAD, 256>>>(W, a, b);
    bprep_kernel<<<O_DIM, 512>>>(W);
    prepx_kernel<<<VPAD / 8, 256>>>(x);
    gather_kernel<<<V_N / 2, 256>>>(adj);
    dim3 ggrid(VPAD / GM, O_DIM / GN);
    gemm_mma_kernel<<<ggrid, 128, SMEM_SZ>>>(out);
}

// round 7
// speedup vs baseline: 1.2404x; 1.2404x over previous
#include <cuda_runtime.h>
#include <cuda_bf16.h>
#include <cuda_fp16.h>
#include <math.h>
#include <cstdint>

// Problem constants (fixed by setup_inputs)
#define V_N   20000
#define VPAD  20096          // multiple of 128
#define D_K   256
#define NHEAD 4
#define O_DIM 128
#define KCAT  1024           // NHEAD * D_K  (GEMM K)
#define KNBR  16

// ---------------- scratch (no allocations allowed) ----------------
__device__ __half   g_xh[(size_t)VPAD * D_K];          // x fp16 [v][d], 10.3 MB
__device__ float    g_attn[NHEAD * V_N];
__device__ float    g_wa[NHEAD * D_K];
__device__ float    g_bbar[O_DIM];
__device__ uint32_t g_Y[(size_t)VPAD * (KCAT / 2)];    // Y fp16 [v][k], 41 MB
__device__ uint32_t g_WB[O_DIM * (KCAT / 2)];          // Wcat fp16 [n=o][k], 256 KB
__device__ int      g_adj64;

// ======================= helpers =======================
__device__ __forceinline__ uint32_t smem_u32(const void* p) {
    uint32_t a;
    asm("{ .reg .u64 t; cvta.to.shared.u64 t, %1; cvt.u32.u64 %0, t; }" : "=r"(a) : "l"(p));
    return a;
}
#define SW128(off) ((off) ^ (((off) >> 3) & 0x70))

#define LDSM4(r, addr) \
    asm volatile("ldmatrix.sync.aligned.m8n8.x4.shared.b16 {%0,%1,%2,%3}, [%4];" \
        : "=r"((r)[0]), "=r"((r)[1]), "=r"((r)[2]), "=r"((r)[3]) : "r"(addr))

#define MMAF16(c, a, b) \
    asm volatile("mma.sync.aligned.m16n8k16.row.col.f32.f16.f16.f32 " \
        "{%0,%1,%2,%3}, {%4,%5,%6,%7}, {%8,%9}, {%0,%1,%2,%3};" \
        : "+f"((c)[0]), "+f"((c)[1]), "+f"((c)[2]), "+f"((c)[3]) \
        : "r"((a)[0]), "r"((a)[1]), "r"((a)[2]), "r"((a)[3]), "r"((b)[0]), "r"((b)[1]))

#define CP_ASYNC16(dst, src) \
    asm volatile("cp.async.cg.shared.global [%0], [%1], 16;" :: "r"(dst), "l"(src))

// ---------------- adj dtype detection ----------------
__global__ void detect_adj_kernel(const void* __restrict__ adj) {
    const long long* p = (const long long*)adj;
    int ok = 1;
    for (int i = 0; i < 64; i++) {
        long long v = p[i];
        if (v < 0 || v > (long long)V_N) { ok = 0; break; }
    }
    g_adj64 = ok;
}

// ---------------- wa[h,d] = sum_o W[h,d,o]*a[h,o]; bbar ----------------
__global__ void wa_kernel(const float* __restrict__ W, const float* __restrict__ a,
                          const float* __restrict__ b) {
    int h = blockIdx.x;
    int d = threadIdx.x;
    const float* Wd = W + ((size_t)h * D_K + d) * O_DIM;
    const float* ah = a + h * O_DIM;
    float s = 0.f;
    #pragma unroll 8
    for (int o = 0; o < O_DIM; o++) s += Wd[o] * ah[o];
    g_wa[h * D_K + d] = s;
    if (h == 0 && d < O_DIM)
        g_bbar[d] = 0.25f * (b[d] + b[O_DIM + d] + b[2 * O_DIM + d] + b[3 * O_DIM + d]);
}

// ---------------- B repack: Wcat[n=o][k=h*256+d] -> fp16 ----------------
__global__ void bprep_kernel(const float* __restrict__ W) {
    int o = blockIdx.x;             // 0..127
    int q = threadIdx.x;            // 0..511 -> k pair (2q, 2q+1)
    int k = 2 * q;
    int h = k >> 8, d = k & 255;
    float w0 = W[((size_t)h * D_K + d)     * O_DIM + o];
    float w1 = W[((size_t)h * D_K + d + 1) * O_DIM + o];
    __half2 p = __float22half2_rn(make_float2(w0, w1));
    g_WB[o * (KCAT / 2) + q] = *(uint32_t*)&p;
}

// ---------------- x prep: fp16 convert + fused attn dots ----------------
__global__ __launch_bounds__(256) void prepx_kernel(const float* __restrict__ x) {
    __shared__ float swa[NHEAD * D_K];
    int tid = threadIdx.x;
    for (int i = tid; i < NHEAD * D_K; i += 256) swa[i] = g_wa[i];
    __syncthreads();

    int wid = tid >> 5, lane = tid & 31;
    int v  = blockIdx.x * 8 + wid;
    int d0 = lane * 8;

    float4 v0 = make_float4(0.f, 0.f, 0.f, 0.f), v1 = v0;
    if (v < V_N) {
        const float* xp = x + (size_t)v * D_K + d0;
        v0 = *(const float4*)xp;
        v1 = *(const float4*)(xp + 4);
    }
    float f[8] = {v0.x, v0.y, v0.z, v0.w, v1.x, v1.y, v1.z, v1.w};
    __half2 p0 = __float22half2_rn(make_float2(f[0], f[1]));
    __half2 p1 = __float22half2_rn(make_float2(f[2], f[3]));
    __half2 p2 = __float22half2_rn(make_float2(f[4], f[5]));
    __half2 p3 = __float22half2_rn(make_float2(f[6], f[7]));
    ((uint4*)g_xh)[(size_t)v * 32 + lane] =
        make_uint4(*(uint32_t*)&p0, *(uint32_t*)&p1, *(uint32_t*)&p2, *(uint32_t*)&p3);

    #pragma unroll
    for (int h = 0; h < NHEAD; h++) {
        const float* wah = swa + h * D_K + d0;
        float s = 0.f;
        #pragma unroll
        for (int j = 0; j < 8; j++) s += f[j] * wah[j];
        #pragma unroll
        for (int off = 16; off; off >>= 1) s += __shfl_xor_sync(0xffffffffu, s, off);
        if (lane == 0 && v < V_N) g_attn[h * V_N + v] = s;
    }
}

// ---------------- gather: softmax coefs + x-space aggregation -> Y fp16 ----------------
// 2 nodes per 256-thread block; 128 threads per node, thread owns d-pair.
__global__ __launch_bounds__(256) void gather_kernel(const void* __restrict__ adj) {
    int local = threadIdx.x >> 7;
    int t     = threadIdx.x & 127;
    int v     = blockIdx.x * 2 + local;

    __shared__ float s_coef[2][NHEAD * KNBR];
    __shared__ int   s_idx [2][KNBR];

    if (t < 64) {
        int k = t & 15;
        int h = t >> 4;
        long long a;
        if (g_adj64) a = ((const long long*)adj)[(size_t)v * KNBR + k];
        else         a = (long long)((const int*)adj)[(size_t)v * KNBR + k];
        bool pad = (a >= (long long)V_N) || (a < 0);
        int n = pad ? 0 : (int)a;
        float sc = pad ? -1e9f : g_attn[h * V_N + n];

        float mx = sc;
        #pragma unroll
        for (int off = 8; off; off >>= 1)
            mx = fmaxf(mx, __shfl_xor_sync(0xffffffffu, mx, off));
        float e = __expf(sc - mx);
        float sum = e;
        #pragma unroll
        for (int off = 8; off; off >>= 1)
            sum += __shfl_xor_sync(0xffffffffu, sum, off);
        s_coef[local][t] = pad ? 0.f : (e / sum);
        if (h == 0) s_idx[local][k] = n;
    }
    __syncthreads();

    const __half2* xh2 = (const __half2*)g_xh;
    float2 acc[NHEAD];
    #pragma unroll
    for (int h = 0; h < NHEAD; h++) acc[h] = make_float2(0.f, 0.f);

    const float* cf = s_coef[local];
    const int*   ix = s_idx [local];
    #pragma unroll
    for (int k = 0; k < KNBR; k++) {
        int n = ix[k];
        float2 fv = __half22float2(__ldg(xh2 + (size_t)n * 128 + t));
        #pragma unroll
        for (int h = 0; h < NHEAD; h++) {
            float c = cf[h * KNBR + k];
            acc[h].x = fmaf(c, fv.x, acc[h].x);
            acc[h].y = fmaf(c, fv.y, acc[h].y);
        }
    }
    #pragma unroll
    for (int h = 0; h < NHEAD; h++) {
        __half2 p = __float22half2_rn(make_float2(acc[h].x, acc[h].y));
        g_Y[(size_t)v * (KCAT / 2) + h * 128 + t] = *(uint32_t*)&p;
    }
}

// ---------------- GEMM: out = relu(0.25 * Y @ Wcat^T + bbar) ----------------
// [VPAD, 1024] x [1024, 128]; BM=128, BN=128 (full N), KC=64, 256 thr, 2-stage.
#define GM 128
#define GN 128
#define KC 64
#define NCHUNK (KCAT / KC)   // 16
#define BUFSZ  32768         // A 16K + B 16K
#define SOA    0
#define SOB    16384
#define SMEM_SZ (2 * BUFSZ)  // 65536

__device__ __forceinline__ void load_chunk(uint32_t sb, int buf, int kc,
                                           int m0, int tid) {
    uint32_t base = sb + buf * BUFSZ;
    #pragma unroll
    for (int i = 0; i < 4; i++) {
        int idx = tid + i * 256;       // 1024 (row,seg) pairs
        int row = idx >> 3, seg = idx & 7;
        uint32_t sw = SW128((uint32_t)(row * 128 + seg * 16));
        size_t   ao = (size_t)(m0 + row) * 128 + kc * 8 + seg;   // uint4 units
        size_t   bo = (size_t)row * 128 + kc * 8 + seg;
        CP_ASYNC16(base + SOA + sw, (const uint4*)g_Y  + ao);
        CP_ASYNC16(base + SOB + sw, (const uint4*)g_WB + bo);
    }
    asm volatile("cp.async.commit_group;" ::: "memory");
}

__global__ __launch_bounds__(256) void gemm_mma_kernel(float* __restrict__ out) {
    extern __shared__ char smem[];
    uint32_t sb = smem_u32(smem);
    int tid = threadIdx.x, wid = tid >> 5, lane = tid & 31;
    int m0 = blockIdx.x * GM;
    int wm = (wid & 3) * 32, wn = (wid >> 2) * 64;

    float acc[2][8][4];
    #pragma unroll
    for (int i = 0; i < 2; i++)
        #pragma unroll
        for (int j = 0; j < 8; j++)
            #pragma unroll
            for (int q = 0; q < 4; q++) acc[i][j][q] = 0.f;

    int lrA = lane & 15;
    int hA  = lane >> 4;
    int lrB = (lane & 7) + ((lane >> 4) << 3);
    int hB  = (lane >> 3) & 1;

    load_chunk(sb, 0, 0, m0, tid);

    for (int kc = 0; kc < NCHUNK; kc++) {
        if (kc + 1 < NCHUNK) {
            load_chunk(sb, (kc + 1) & 1, kc + 1, m0, tid);
            asm volatile("cp.async.wait_group 1;" ::: "memory");
        } else {
            asm volatile("cp.async.wait_group 0;" ::: "memory");
        }
        __syncthreads();

        uint32_t base = sb + (kc & 1) * BUFSZ;
        #pragma unroll
        for (int ks = 0; ks < 4; ks++) {
            uint32_t a_f[2][4];
            #pragma unroll
            for (int mt = 0; mt < 2; mt++) {
                uint32_t off = SW128((uint32_t)((wm + mt * 16 + lrA) * 128 + ks * 32 + hA * 16));
                LDSM4(a_f[mt], base + SOA + off);
            }
            #pragma unroll
            for (int p = 0; p < 4; p++) {
                uint32_t bf[4];
                uint32_t off = SW128((uint32_t)((wn + p * 16 + lrB) * 128 + ks * 32 + hB * 16));
                LDSM4(bf, base + SOB + off);
                #pragma unroll
                for (int mt = 0; mt < 2; mt++) {
                    MMAF16(acc[mt][2 * p],     a_f[mt], &bf[0]);
                    MMAF16(acc[mt][2 * p + 1], a_f[mt], &bf[2]);
                }
            }
        }
        __syncthreads();
    }

    // epilogue: out = relu(0.25*acc + bbar), guarded rows
    int g  = lane >> 2;
    int t2 = (lane & 3) * 2;
    #pragma unroll
    for (int mt = 0; mt < 2; mt++) {
        int r0 = m0 + wm + mt * 16 + g;
        #pragma unroll
        for (int nt = 0; nt < 8; nt++) {
            int c = wn + nt * 8 + t2;
            float bx = g_bbar[c], by = g_bbar[c + 1];
            if (r0 < V_N) {
                float rx = fmaxf(fmaf(acc[mt][nt][0], 0.25f, bx), 0.f);
                float ry = fmaxf(fmaf(acc[mt][nt][1], 0.25f, by), 0.f);
                *(float2*)(out + (size_t)r0 * O_DIM + c) = make_float2(rx, ry);
            }
            if (r0 + 8 < V_N) {
                float rx = fmaxf(fmaf(acc[mt][nt][2], 0.25f, bx), 0.f);
                float ry = fmaxf(fmaf(acc[mt][nt][3], 0.25f, by), 0.f);
                *(float2*)(out + (size_t)(r0 + 8) * O_DIM + c) = make_float2(rx, ry);
            }
        }
    }
}

// ---------------- launch ----------------
extern "C" void kernel_launch(void* const* d_in, const int* in_sizes, int n_in,
                              void* d_out, int out_size) {
    const float* x   = (const float*)d_in[0];   // [V, D]
    const float* W   = (const float*)d_in[1];   // [H, D, O]
    const float* a   = (const float*)d_in[2];   // [H, O]
    const float* b   = (const float*)d_in[3];   // [H, O]
    const void*  adj = d_in[4];                 // [V, K] int32 or int64
    float* out = (float*)d_out;                 // [V, O]

    cudaFuncSetAttribute(gemm_mma_kernel, cudaFuncAttributeMaxDynamicSharedMemorySize, SMEM_SZ);

    detect_adj_kernel<<<1, 1>>>(adj);
    wa_kernel<<<NHEAD, 256>>>(W, a, b);
    bprep_kernel<<<O_DIM, 512>>>(W);
    prepx_kernel<<<VPAD / 8, 256>>>(x);
    gather_kernel<<<V_N / 2, 256>>>(adj);
    gemm_mma_kernel<<<VPAD / GM, 256, SMEM_SZ>>>(out);
}

// round 8
// speedup vs baseline: 1.3705x; 1.1049x over previous
#include <cuda_runtime.h>
#include <cuda_bf16.h>
#include <cuda_fp16.h>
#include <math.h>
#include <cstdint>

// Problem constants (fixed by setup_inputs)
#define V_N   20000
#define VPAD  20096          // multiple of 128
#define D_K   256
#define NHEAD 4
#define O_DIM 128
#define KCAT  1024           // NHEAD * D_K  (GEMM K)
#define KNBR  16

// ---------------- scratch (no allocations allowed) ----------------
__device__ __half   g_xh[(size_t)VPAD * D_K];          // x fp16 [v][d], 10.3 MB
__device__ float    g_attn[NHEAD * V_N];
__device__ float    g_wa[NHEAD * D_K];
__device__ float    g_bbar[O_DIM];
__device__ uint32_t g_Y[(size_t)VPAD * (KCAT / 2)];    // Y fp16 [v][k], 41 MB
__device__ uint32_t g_WB[O_DIM * (KCAT / 2)];          // Wcat fp16 [n=o][k], 256 KB
__device__ int      g_adj64;

// ======================= helpers =======================
__device__ __forceinline__ uint32_t smem_u32(const void* p) {
    uint32_t a;
    asm("{ .reg .u64 t; cvta.to.shared.u64 t, %1; cvt.u32.u64 %0, t; }" : "=r"(a) : "l"(p));
    return a;
}
#define SW128(off) ((off) ^ (((off) >> 3) & 0x70))

#define LDSM4(r, addr) \
    asm volatile("ldmatrix.sync.aligned.m8n8.x4.shared.b16 {%0,%1,%2,%3}, [%4];" \
        : "=r"((r)[0]), "=r"((r)[1]), "=r"((r)[2]), "=r"((r)[3]) : "r"(addr))

#define MMAF16(c, a, b) \
    asm volatile("mma.sync.aligned.m16n8k16.row.col.f32.f16.f16.f32 " \
        "{%0,%1,%2,%3}, {%4,%5,%6,%7}, {%8,%9}, {%0,%1,%2,%3};" \
        : "+f"((c)[0]), "+f"((c)[1]), "+f"((c)[2]), "+f"((c)[3]) \
        : "r"((a)[0]), "r"((a)[1]), "r"((a)[2]), "r"((a)[3]), "r"((b)[0]), "r"((b)[1]))

#define CP_ASYNC16(dst, src) \
    asm volatile("cp.async.cg.shared.global [%0], [%1], 16;" :: "r"(dst), "l"(src))

// ---------------- adj dtype detection ----------------
__global__ void detect_adj_kernel(const void* __restrict__ adj) {
    const long long* p = (const long long*)adj;
    int ok = 1;
    for (int i = 0; i < 64; i++) {
        long long v = p[i];
        if (v < 0 || v > (long long)V_N) { ok = 0; break; }
    }
    g_adj64 = ok;
}

// ---------------- wa[h,d] = sum_o W[h,d,o]*a[h,o]; bbar ----------------
__global__ void wa_kernel(const float* __restrict__ W, const float* __restrict__ a,
                          const float* __restrict__ b) {
    int h = blockIdx.x;
    int d = threadIdx.x;
    const float* Wd = W + ((size_t)h * D_K + d) * O_DIM;
    const float* ah = a + h * O_DIM;
    float s = 0.f;
    #pragma unroll 8
    for (int o = 0; o < O_DIM; o++) s += Wd[o] * ah[o];
    g_wa[h * D_K + d] = s;
    if (h == 0 && d < O_DIM)
        g_bbar[d] = 0.25f * (b[d] + b[O_DIM + d] + b[2 * O_DIM + d] + b[3 * O_DIM + d]);
}

// ---------------- B repack: Wcat[n=o][k=h*256+d] -> fp16 ----------------
__global__ void bprep_kernel(const float* __restrict__ W) {
    int o = blockIdx.x;             // 0..127
    int q = threadIdx.x;            // 0..511 -> k pair (2q, 2q+1)
    int k = 2 * q;
    int h = k >> 8, d = k & 255;
    float w0 = W[((size_t)h * D_K + d)     * O_DIM + o];
    float w1 = W[((size_t)h * D_K + d + 1) * O_DIM + o];
    __half2 p = __float22half2_rn(make_float2(w0, w1));
    g_WB[o * (KCAT / 2) + q] = *(uint32_t*)&p;
}

// ---------------- x prep: fp16 convert + fused attn dots (4 rows/warp, MLP) ----------------
__global__ __launch_bounds__(256) void prepx_kernel(const float* __restrict__ x) {
    __shared__ float swa[NHEAD * D_K];
    int tid = threadIdx.x;
    for (int i = tid; i < NHEAD * D_K; i += 256) swa[i] = g_wa[i];
    __syncthreads();

    int wid = tid >> 5, lane = tid & 31;
    int vbase = blockIdx.x * 32 + wid * 4;
    int d0 = lane * 8;

    // issue all 8 loads up front for MLP
    float4 va[4], vb[4];
    #pragma unroll
    for (int r = 0; r < 4; r++) {
        int v = vbase + r;
        if (v < V_N) {
            const float* xp = x + (size_t)v * D_K + d0;
            va[r] = *(const float4*)xp;
            vb[r] = *(const float4*)(xp + 4);
        } else {
            va[r] = make_float4(0.f, 0.f, 0.f, 0.f);
            vb[r] = va[r];
        }
    }

    #pragma unroll
    for (int r = 0; r < 4; r++) {
        int v = vbase + r;
        float f[8] = {va[r].x, va[r].y, va[r].z, va[r].w,
                      vb[r].x, vb[r].y, vb[r].z, vb[r].w};
        __half2 p0 = __float22half2_rn(make_float2(f[0], f[1]));
        __half2 p1 = __float22half2_rn(make_float2(f[2], f[3]));
        __half2 p2 = __float22half2_rn(make_float2(f[4], f[5]));
        __half2 p3 = __float22half2_rn(make_float2(f[6], f[7]));
        ((uint4*)g_xh)[(size_t)v * 32 + lane] =
            make_uint4(*(uint32_t*)&p0, *(uint32_t*)&p1, *(uint32_t*)&p2, *(uint32_t*)&p3);

        #pragma unroll
        for (int h = 0; h < NHEAD; h++) {
            const float* wah = swa + h * D_K + d0;
            float s = 0.f;
            #pragma unroll
            for (int j = 0; j < 8; j++) s += f[j] * wah[j];
            #pragma unroll
            for (int off = 16; off; off >>= 1) s += __shfl_xor_sync(0xffffffffu, s, off);
            if (lane == 0 && v < V_N) g_attn[h * V_N + v] = s;
        }
    }
}

// ---------------- gather: softmax coefs + x-space aggregation -> Y fp16 ----------------
// 2 nodes per 256-thread block; 128 threads per node; coefs packed [k][h] for float4 loads.
__global__ __launch_bounds__(256) void gather_kernel(const void* __restrict__ adj) {
    int local = threadIdx.x >> 7;
    int t     = threadIdx.x & 127;
    int v     = blockIdx.x * 2 + local;

    __shared__ float s_coef[2][KNBR * NHEAD];   // [k*4 + h]
    __shared__ int   s_idx [2][KNBR];

    if (t < 64) {
        int k = t & 15;
        int h = t >> 4;
        long long a;
        if (g_adj64) a = ((const long long*)adj)[(size_t)v * KNBR + k];
        else         a = (long long)((const int*)adj)[(size_t)v * KNBR + k];
        bool pad = (a >= (long long)V_N) || (a < 0);
        int n = pad ? 0 : (int)a;
        float sc = pad ? -1e9f : g_attn[h * V_N + n];

        float mx = sc;
        #pragma unroll
        for (int off = 8; off; off >>= 1)
            mx = fmaxf(mx, __shfl_xor_sync(0xffffffffu, mx, off));
        float e = __expf(sc - mx);
        float sum = e;
        #pragma unroll
        for (int off = 8; off; off >>= 1)
            sum += __shfl_xor_sync(0xffffffffu, sum, off);
        s_coef[local][k * 4 + h] = pad ? 0.f : (e / sum);
        if (h == 0) s_idx[local][k] = n;
    }
    __syncthreads();

    const __half2* xh2 = (const __half2*)g_xh;
    float2 acc[NHEAD];
    #pragma unroll
    for (int h = 0; h < NHEAD; h++) acc[h] = make_float2(0.f, 0.f);

    const float* cf = s_coef[local];
    const int*   ix = s_idx [local];
    #pragma unroll
    for (int k = 0; k < KNBR; k++) {
        int n = ix[k];
        float2 fv = __half22float2(__ldg(xh2 + (size_t)n * 128 + t));
        float4 c4 = *(const float4*)(cf + k * 4);   // one LDS.128 for all 4 heads
        acc[0].x = fmaf(c4.x, fv.x, acc[0].x);  acc[0].y = fmaf(c4.x, fv.y, acc[0].y);
        acc[1].x = fmaf(c4.y, fv.x, acc[1].x);  acc[1].y = fmaf(c4.y, fv.y, acc[1].y);
        acc[2].x = fmaf(c4.z, fv.x, acc[2].x);  acc[2].y = fmaf(c4.z, fv.y, acc[2].y);
        acc[3].x = fmaf(c4.w, fv.x, acc[3].x);  acc[3].y = fmaf(c4.w, fv.y, acc[3].y);
    }
    #pragma unroll
    for (int h = 0; h < NHEAD; h++) {
        __half2 p = __float22half2_rn(make_float2(acc[h].x, acc[h].y));
        g_Y[(size_t)v * (KCAT / 2) + h * 128 + t] = *(uint32_t*)&p;
    }
}

// ---------------- GEMM: out = relu(0.25 * Y @ Wcat^T + bbar) ----------------
// [VPAD, 1024] x [1024, 128]; BM=64, BN=128, KC=64, 128 thr, 2-stage, 4 CTA/SM.
#define GM 64
#define GN 128
#define KC 64
#define NCHUNK (KCAT / KC)   // 16
#define BUFSZ  24576         // A 8K + B 16K
#define SOA    0
#define SOB    8192
#define SMEM_SZ (2 * BUFSZ)  // 49152

__device__ __forceinline__ void load_chunk(uint32_t sb, int buf, int kc,
                                           int m0, int tid) {
    uint32_t base = sb + buf * BUFSZ;
    // A: 512 uint4 (64 rows x 8 segs)
    #pragma unroll
    for (int i = 0; i < 4; i++) {
        int idx = tid + i * 128;
        int row = idx >> 3, seg = idx & 7;
        uint32_t sw = SW128((uint32_t)(row * 128 + seg * 16));
        CP_ASYNC16(base + SOA + sw, (const uint4*)g_Y + (size_t)(m0 + row) * 128 + kc * 8 + seg);
    }
    // B: 1024 uint4 (128 rows x 8 segs)
    #pragma unroll
    for (int i = 0; i < 8; i++) {
        int idx = tid + i * 128;
        int n = idx >> 3, seg = idx & 7;
        uint32_t sw = SW128((uint32_t)(n * 128 + seg * 16));
        CP_ASYNC16(base + SOB + sw, (const uint4*)g_WB + (size_t)n * 128 + kc * 8 + seg);
    }
    asm volatile("cp.async.commit_group;" ::: "memory");
}

__global__ __launch_bounds__(128) void gemm_mma_kernel(float* __restrict__ out) {
    extern __shared__ char smem[];
    uint32_t sb = smem_u32(smem);
    int tid = threadIdx.x, wid = tid >> 5, lane = tid & 31;
    int m0 = blockIdx.x * GM;
    int wm = (wid & 1) * 32, wn = (wid >> 1) * 64;

    float acc[2][8][4];
    #pragma unroll
    for (int i = 0; i < 2; i++)
        #pragma unroll
        for (int j = 0; j < 8; j++)
            #pragma unroll
            for (int q = 0; q < 4; q++) acc[i][j][q] = 0.f;

    int lrA = lane & 15;
    int hA  = lane >> 4;
    int lrB = (lane & 7) + ((lane >> 4) << 3);
    int hB  = (lane >> 3) & 1;

    load_chunk(sb, 0, 0, m0, tid);

    for (int kc = 0; kc < NCHUNK; kc++) {
        if (kc + 1 < NCHUNK) {
            load_chunk(sb, (kc + 1) & 1, kc + 1, m0, tid);
            asm volatile("cp.async.wait_group 1;" ::: "memory");
        } else {
            asm volatile("cp.async.wait_group 0;" ::: "memory");
        }
        __syncthreads();

        uint32_t base = sb + (kc & 1) * BUFSZ;
        #pragma unroll
        for (int ks = 0; ks < 4; ks++) {
            uint32_t a_f[2][4];
            #pragma unroll
            for (int mt = 0; mt < 2; mt++) {
                uint32_t off = SW128((uint32_t)((wm + mt * 16 + lrA) * 128 + ks * 32 + hA * 16));
                LDSM4(a_f[mt], base + SOA + off);
            }
            #pragma unroll
            for (int p = 0; p < 4; p++) {
                uint32_t bf[4];
                uint32_t off = SW128((uint32_t)((wn + p * 16 + lrB) * 128 + ks * 32 + hB * 16));
                LDSM4(bf, base + SOB + off);
                #pragma unroll
                for (int mt = 0; mt < 2; mt++) {
                    MMAF16(acc[mt][2 * p],     a_f[mt], &bf[0]);
                    MMAF16(acc[mt][2 * p + 1], a_f[mt], &bf[2]);
                }
            }
        }
        __syncthreads();
    }

    // epilogue: out = relu(0.25*acc + bbar), guarded rows
    int g  = lane >> 2;
    int t2 = (lane & 3) * 2;
    #pragma unroll
    for (int mt = 0; mt < 2; mt++) {
        int r0 = m0 + wm + mt * 16 + g;
        #pragma unroll
        for (int nt = 0; nt < 8; nt++) {
            int c = wn + nt * 8 + t2;
            float bx = g_bbar[c], by = g_bbar[c + 1];
            if (r0 < V_N) {
                float rx = fmaxf(fmaf(acc[mt][nt][0], 0.25f, bx), 0.f);
                float ry = fmaxf(fmaf(acc[mt][nt][1], 0.25f, by), 0.f);
                *(float2*)(out + (size_t)r0 * O_DIM + c) = make_float2(rx, ry);
            }
            if (r0 + 8 < V_N) {
                float rx = fmaxf(fmaf(acc[mt][nt][2], 0.25f, bx), 0.f);
                float ry = fmaxf(fmaf(acc[mt][nt][3], 0.25f, by), 0.f);
                *(float2*)(out + (size_t)(r0 + 8) * O_DIM + c) = make_float2(rx, ry);
            }
        }
    }
}

// ---------------- launch ----------------
extern "C" void kernel_launch(void* const* d_in, const int* in_sizes, int n_in,
                              void* d_out, int out_size) {
    const float* x   = (const float*)d_in[0];   // [V, D]
    const float* W   = (const float*)d_in[1];   // [H, D, O]
    const float* a   = (const float*)d_in[2];   // [H, O]
    const float* b   = (const float*)d_in[3];   // [H, O]
    const void*  adj = d_in[4];                 // [V, K] int32 or int64
    float* out = (float*)d_out;                 // [V, O]

    cudaFuncSetAttribute(gemm_mma_kernel, cudaFuncAttributeMaxDynamicSharedMemorySize, SMEM_SZ);

    detect_adj_kernel<<<1, 1>>>(adj);
    wa_kernel<<<NHEAD, 256>>>(W, a, b);
    bprep_kernel<<<O_DIM, 512>>>(W);
    prepx_kernel<<<VPAD / 32, 256>>>(x);
    gather_kernel<<<V_N / 2, 256>>>(adj);
    gemm_mma_kernel<<<VPAD / GM, 128, SMEM_SZ>>>(out);
}

// round 9
// speedup vs baseline: 1.4737x; 1.0753x over previous
#include <cuda_runtime.h>
#include <cuda_bf16.h>
#include <cuda_fp16.h>
#include <math.h>
#include <cstdint>

// Problem constants (fixed by setup_inputs)
#define V_N   20000
#define VPAD  20096          // multiple of 128
#define D_K   256
#define NHEAD 4
#define O_DIM 128
#define KCAT  1024           // NHEAD * D_K  (GEMM K)
#define KNBR  16

// ---------------- scratch (no allocations allowed) ----------------
__device__ __half   g_xh[(size_t)VPAD * D_K];          // x fp16 [v][d], 10.3 MB
__device__ float    g_attn[(size_t)V_N * NHEAD];       // attn [v][h]  (float4 rows)
__device__ float    g_wa[NHEAD * D_K];
__device__ float    g_bbar[O_DIM];
__device__ uint32_t g_Y[(size_t)VPAD * (KCAT / 2)];    // Y fp16 [v][k], 41 MB
__device__ uint32_t g_WB[O_DIM * (KCAT / 2)];          // Wcat fp16 [n=o][k], 256 KB
__device__ int      g_adj64;

// ======================= helpers =======================
__device__ __forceinline__ uint32_t smem_u32(const void* p) {
    uint32_t a;
    asm("{ .reg .u64 t; cvta.to.shared.u64 t, %1; cvt.u32.u64 %0, t; }" : "=r"(a) : "l"(p));
    return a;
}
#define SW128(off) ((off) ^ (((off) >> 3) & 0x70))

#define LDSM4(r, addr) \
    asm volatile("ldmatrix.sync.aligned.m8n8.x4.shared.b16 {%0,%1,%2,%3}, [%4];" \
        : "=r"((r)[0]), "=r"((r)[1]), "=r"((r)[2]), "=r"((r)[3]) : "r"(addr))

#define MMAF16(c, a, b) \
    asm volatile("mma.sync.aligned.m16n8k16.row.col.f32.f16.f16.f32 " \
        "{%0,%1,%2,%3}, {%4,%5,%6,%7}, {%8,%9}, {%0,%1,%2,%3};" \
        : "+f"((c)[0]), "+f"((c)[1]), "+f"((c)[2]), "+f"((c)[3]) \
        : "r"((a)[0]), "r"((a)[1]), "r"((a)[2]), "r"((a)[3]), "r"((b)[0]), "r"((b)[1]))

#define CP_ASYNC16(dst, src) \
    asm volatile("cp.async.cg.shared.global [%0], [%1], 16;" :: "r"(dst), "l"(src))

// ---------------- merged prep: bprep (blk 0..127), wa (128..131), detect (132) ----------------
__global__ __launch_bounds__(256) void prep_misc_kernel(const float* __restrict__ W,
                                                        const float* __restrict__ a,
                                                        const float* __restrict__ b,
                                                        const void* __restrict__ adj) {
    int blk = blockIdx.x;
    int tid = threadIdx.x;
    if (blk < 128) {
        // B repack: Wcat[n=o][k=h*256+d] -> fp16
        int o = blk;
        #pragma unroll
        for (int i = 0; i < 2; i++) {
            int q = tid + i * 256;          // 0..511 -> k pair (2q, 2q+1)
            int k = 2 * q;
            int h = k >> 8, d = k & 255;
            float w0 = W[((size_t)h * D_K + d)     * O_DIM + o];
            float w1 = W[((size_t)h * D_K + d + 1) * O_DIM + o];
            __half2 p = __float22half2_rn(make_float2(w0, w1));
            g_WB[o * (KCAT / 2) + q] = *(uint32_t*)&p;
        }
    } else if (blk < 132) {
        // wa[h,d] = sum_o W[h,d,o]*a[h,o]; bbar
        int h = blk - 128;
        int d = tid;
        const float* Wd = W + ((size_t)h * D_K + d) * O_DIM;
        const float* ah = a + h * O_DIM;
        float s = 0.f;
        #pragma unroll 8
        for (int o = 0; o < O_DIM; o++) s += Wd[o] * ah[o];
        g_wa[h * D_K + d] = s;
        if (h == 0 && d < O_DIM)
            g_bbar[d] = 0.25f * (b[d] + b[O_DIM + d] + b[2 * O_DIM + d] + b[3 * O_DIM + d]);
    } else {
        if (tid == 0) {
            const long long* p = (const long long*)adj;
            int ok = 1;
            for (int i = 0; i < 64; i++) {
                long long v = p[i];
                if (v < 0 || v > (long long)V_N) { ok = 0; break; }
            }
            g_adj64 = ok;
        }
    }
}

// ---------------- x prep: fp16 convert + fused attn dots (wa in registers) ----------------
// 2 rows per warp, 16 rows per 256-thread block.
__global__ __launch_bounds__(256) void prepx_kernel(const float* __restrict__ x) {
    int tid  = threadIdx.x;
    int wid  = tid >> 5, lane = tid & 31;
    int d0   = lane * 8;

    // hoist wa into registers: wra/wrb[h] cover wa[h][d0..d0+7]
    float4 wra[NHEAD], wrb[NHEAD];
    #pragma unroll
    for (int h = 0; h < NHEAD; h++) {
        const float* wp = g_wa + h * D_K + d0;
        wra[h] = *(const float4*)wp;
        wrb[h] = *(const float4*)(wp + 4);
    }

    int vbase = blockIdx.x * 16 + wid * 2;
    #pragma unroll
    for (int r = 0; r < 2; r++) {
        int v = vbase + r;
        if (v >= V_N) continue;
        const float* xp = x + (size_t)v * D_K + d0;
        float4 va = *(const float4*)xp;
        float4 vb = *(const float4*)(xp + 4);

        __half2 p0 = __float22half2_rn(make_float2(va.x, va.y));
        __half2 p1 = __float22half2_rn(make_float2(va.z, va.w));
        __half2 p2 = __float22half2_rn(make_float2(vb.x, vb.y));
        __half2 p3 = __float22half2_rn(make_float2(vb.z, vb.w));
        ((uint4*)g_xh)[(size_t)v * 32 + lane] =
            make_uint4(*(uint32_t*)&p0, *(uint32_t*)&p1, *(uint32_t*)&p2, *(uint32_t*)&p3);

        float res[NHEAD];
        #pragma unroll
        for (int h = 0; h < NHEAD; h++) {
            float s = va.x * wra[h].x + va.y * wra[h].y + va.z * wra[h].z + va.w * wra[h].w
                    + vb.x * wrb[h].x + vb.y * wrb[h].y + vb.z * wrb[h].z + vb.w * wrb[h].w;
            #pragma unroll
            for (int off = 16; off; off >>= 1) s += __shfl_xor_sync(0xffffffffu, s, off);
            res[h] = s;
        }
        if (lane == 0)
            *(float4*)(g_attn + (size_t)v * NHEAD) =
                make_float4(res[0], res[1], res[2], res[3]);
    }
}

// ---------------- gather: softmax coefs + x-space aggregation -> Y fp16 ----------------
// 2 nodes per 256-thread block; 128 threads per node; coefs packed [k][h] for float4 loads.
__global__ __launch_bounds__(256) void gather_kernel(const void* __restrict__ adj) {
    int local = threadIdx.x >> 7;
    int t     = threadIdx.x & 127;
    int v     = blockIdx.x * 2 + local;

    __shared__ float s_coef[2][KNBR * NHEAD];   // [k*4 + h]
    __shared__ int   s_idx [2][KNBR];

    if (t < 64) {
        int k = t & 15;
        int h = t >> 4;
        long long a;
        if (g_adj64) a = ((const long long*)adj)[(size_t)v * KNBR + k];
        else         a = (long long)((const int*)adj)[(size_t)v * KNBR + k];
        bool pad = (a >= (long long)V_N) || (a < 0);
        int n = pad ? 0 : (int)a;
        float sc = pad ? -1e9f : g_attn[(size_t)n * NHEAD + h];

        float mx = sc;
        #pragma unroll
        for (int off = 8; off; off >>= 1)
            mx = fmaxf(mx, __shfl_xor_sync(0xffffffffu, mx, off));
        float e = __expf(sc - mx);
        float sum = e;
        #pragma unroll
        for (int off = 8; off; off >>= 1)
            sum += __shfl_xor_sync(0xffffffffu, sum, off);
        s_coef[local][k * 4 + h] = pad ? 0.f : (e / sum);
        if (h == 0) s_idx[local][k] = n;
    }
    __syncthreads();

    const __half2* xh2 = (const __half2*)g_xh;
    float2 acc[NHEAD];
    #pragma unroll
    for (int h = 0; h < NHEAD; h++) acc[h] = make_float2(0.f, 0.f);

    const float* cf = s_coef[local];
    const int*   ix = s_idx [local];
    #pragma unroll
    for (int k = 0; k < KNBR; k++) {
        int n = ix[k];
        float2 fv = __half22float2(__ldg(xh2 + (size_t)n * 128 + t));
        float4 c4 = *(const float4*)(cf + k * 4);   // one LDS.128 (broadcast) for 4 heads
        acc[0].x = fmaf(c4.x, fv.x, acc[0].x);  acc[0].y = fmaf(c4.x, fv.y, acc[0].y);
        acc[1].x = fmaf(c4.y, fv.x, acc[1].x);  acc[1].y = fmaf(c4.y, fv.y, acc[1].y);
        acc[2].x = fmaf(c4.z, fv.x, acc[2].x);  acc[2].y = fmaf(c4.z, fv.y, acc[2].y);
        acc[3].x = fmaf(c4.w, fv.x, acc[3].x);  acc[3].y = fmaf(c4.w, fv.y, acc[3].y);
    }
    #pragma unroll
    for (int h = 0; h < NHEAD; h++) {
        __half2 p = __float22half2_rn(make_float2(acc[h].x, acc[h].y));
        g_Y[(size_t)v * (KCAT / 2) + h * 128 + t] = *(uint32_t*)&p;
    }
}

// ---------------- GEMM: out = relu(0.25 * Y @ Wcat^T + bbar) ----------------
// [VPAD, 1024] x [1024, 128]; BM=64, BN=128, KC=64, 128 thr, 2-stage, 4 CTA/SM.
#define GM 64
#define GN 128
#define KC 64
#define NCHUNK (KCAT / KC)   // 16
#define BUFSZ  24576         // A 8K + B 16K
#define SOA    0
#define SOB    8192
#define SMEM_SZ (2 * BUFSZ)  // 49152

__device__ __forceinline__ void load_chunk(uint32_t sb, int buf, int kc,
                                           int m0, int tid) {
    uint32_t base = sb + buf * BUFSZ;
    // A: 512 uint4 (64 rows x 8 segs)
    #pragma unroll
    for (int i = 0; i < 4; i++) {
        int idx = tid + i * 128;
        int row = idx >> 3, seg = idx & 7;
        uint32_t sw = SW128((uint32_t)(row * 128 + seg * 16));
        CP_ASYNC16(base + SOA + sw, (const uint4*)g_Y + (size_t)(m0 + row) * 128 + kc * 8 + seg);
    }
    // B: 1024 uint4 (128 rows x 8 segs)
    #pragma unroll
    for (int i = 0; i < 8; i++) {
        int idx = tid + i * 128;
        int n = idx >> 3, seg = idx & 7;
        uint32_t sw = SW128((uint32_t)(n * 128 + seg * 16));
        CP_ASYNC16(base + SOB + sw, (const uint4*)g_WB + (size_t)n * 128 + kc * 8 + seg);
    }
    asm volatile("cp.async.commit_group;" ::: "memory");
}

__global__ __launch_bounds__(128) void gemm_mma_kernel(float* __restrict__ out) {
    extern __shared__ char smem[];
    uint32_t sb = smem_u32(smem);
    int tid = threadIdx.x, wid = tid >> 5, lane = tid & 31;
    int m0 = blockIdx.x * GM;
    int wm = (wid & 1) * 32, wn = (wid >> 1) * 64;

    float acc[2][8][4];
    #pragma unroll
    for (int i = 0; i < 2; i++)
        #pragma unroll
        for (int j = 0; j < 8; j++)
            #pragma unroll
            for (int q = 0; q < 4; q++) acc[i][j][q] = 0.f;

    int lrA = lane & 15;
    int hA  = lane >> 4;
    int lrB = (lane & 7) + ((lane >> 4) << 3);
    int hB  = (lane >> 3) & 1;

    load_chunk(sb, 0, 0, m0, tid);

    for (int kc = 0; kc < NCHUNK; kc++) {
        if (kc + 1 < NCHUNK) {
            load_chunk(sb, (kc + 1) & 1, kc + 1, m0, tid);
            asm volatile("cp.async.wait_group 1;" ::: "memory");
        } else {
            asm volatile("cp.async.wait_group 0;" ::: "memory");
        }
        __syncthreads();

        uint32_t base = sb + (kc & 1) * BUFSZ;
        #pragma unroll
        for (int ks = 0; ks < 4; ks++) {
            uint32_t a_f[2][4];
            #pragma unroll
            for (int mt = 0; mt < 2; mt++) {
                uint32_t off = SW128((uint32_t)((wm + mt * 16 + lrA) * 128 + ks * 32 + hA * 16));
                LDSM4(a_f[mt], base + SOA + off);
            }
            #pragma unroll
            for (int p = 0; p < 4; p++) {
                uint32_t bf[4];
                uint32_t off = SW128((uint32_t)((wn + p * 16 + lrB) * 128 + ks * 32 + hB * 16));
                LDSM4(bf, base + SOB + off);
                #pragma unroll
                for (int mt = 0; mt < 2; mt++) {
                    MMAF16(acc[mt][2 * p],     a_f[mt], &bf[0]);
                    MMAF16(acc[mt][2 * p + 1], a_f[mt], &bf[2]);
                }
            }
        }
        __syncthreads();
    }

    // epilogue: out = relu(0.25*acc + bbar), guarded rows
    int g  = lane >> 2;
    int t2 = (lane & 3) * 2;
    #pragma unroll
    for (int mt = 0; mt < 2; mt++) {
        int r0 = m0 + wm + mt * 16 + g;
        #pragma unroll
        for (int nt = 0; nt < 8; nt++) {
            int c = wn + nt * 8 + t2;
            float bx = g_bbar[c], by = g_bbar[c + 1];
            if (r0 < V_N) {
                float rx = fmaxf(fmaf(acc[mt][nt][0], 0.25f, bx), 0.f);
                float ry = fmaxf(fmaf(acc[mt][nt][1], 0.25f, by), 0.f);
                *(float2*)(out + (size_t)r0 * O_DIM + c) = make_float2(rx, ry);
            }
            if (r0 + 8 < V_N) {
                float rx = fmaxf(fmaf(acc[mt][nt][2], 0.25f, bx), 0.f);
                float ry = fmaxf(fmaf(acc[mt][nt][3], 0.25f, by), 0.f);
                *(float2*)(out + (size_t)(r0 + 8) * O_DIM + c) = make_float2(rx, ry);
            }
        }
    }
}

// ---------------- launch ----------------
extern "C" void kernel_launch(void* const* d_in, const int* in_sizes, int n_in,
                              void* d_out, int out_size) {
    const float* x   = (const float*)d_in[0];   // [V, D]
    const float* W   = (const float*)d_in[1];   // [H, D, O]
    const float* a   = (const float*)d_in[2];   // [H, O]
    const float* b   = (const float*)d_in[3];   // [H, O]
    const void*  adj = d_in[4];                 // [V, K] int32 or int64
    float* out = (float*)d_out;                 // [V, O]

    cudaFuncSetAttribute(gemm_mma_kernel, cudaFuncAttributeMaxDynamicSharedMemorySize, SMEM_SZ);

    prep_misc_kernel<<<133, 256>>>(W, a, b, adj);
    prepx_kernel<<<VPAD / 16, 256>>>(x);
    gather_kernel<<<V_N / 2, 256>>>(adj);
    gemm_mma_kernel<<<VPAD / GM, 128, SMEM_SZ>>>(out);
}

// round 10
// speedup vs baseline: 1.4794x; 1.0039x over previous
#include <cuda_runtime.h>
#include <cuda_bf16.h>
#include <cuda_fp16.h>
#include <math.h>
#include <cstdint>

// Problem constants (fixed by setup_inputs)
#define V_N   20000
#define VPAD  20096          // multiple of 128
#define D_K   256
#define NHEAD 4
#define O_DIM 128
#define KCAT  1024           // NHEAD * D_K  (GEMM K)
#define KNBR  16

// ---------------- scratch (no allocations allowed) ----------------
__device__ __half   g_xh[(size_t)VPAD * D_K];          // x fp16 [v][d], 10.3 MB
__device__ float    g_attn[(size_t)V_N * NHEAD];       // attn [v][h]  (float4 rows)
__device__ float    g_wa[NHEAD * D_K];
__device__ float    g_bbar[O_DIM];
__device__ uint32_t g_Y[(size_t)VPAD * (KCAT / 2)];    // Y fp16 [v][k], 41 MB
__device__ uint32_t g_WB[O_DIM * (KCAT / 2)];          // Wcat fp16 [n=o][k], 256 KB
__device__ int      g_adj64;

// ======================= helpers =======================
__device__ __forceinline__ uint32_t smem_u32(const void* p) {
    uint32_t a;
    asm("{ .reg .u64 t; cvta.to.shared.u64 t, %1; cvt.u32.u64 %0, t; }" : "=r"(a) : "l"(p));
    return a;
}
#define SW128(off) ((off) ^ (((off) >> 3) & 0x70))

#define LDSM4(r, addr) \
    asm volatile("ldmatrix.sync.aligned.m8n8.x4.shared.b16 {%0,%1,%2,%3}, [%4];" \
        : "=r"((r)[0]), "=r"((r)[1]), "=r"((r)[2]), "=r"((r)[3]) : "r"(addr))

#define MMAF16(c, a, b) \
    asm volatile("mma.sync.aligned.m16n8k16.row.col.f32.f16.f16.f32 " \
        "{%0,%1,%2,%3}, {%4,%5,%6,%7}, {%8,%9}, {%0,%1,%2,%3};" \
        : "+f"((c)[0]), "+f"((c)[1]), "+f"((c)[2]), "+f"((c)[3]) \
        : "r"((a)[0]), "r"((a)[1]), "r"((a)[2]), "r"((a)[3]), "r"((b)[0]), "r"((b)[1]))

#define CP_ASYNC16(dst, src) \
    asm volatile("cp.async.cg.shared.global [%0], [%1], 16;" :: "r"(dst), "l"(src))

// ---------------- merged prep: bprep (blk 0..127), wa (128..131), detect (132) ----------------
__global__ __launch_bounds__(256) void prep_misc_kernel(const float* __restrict__ W,
                                                        const float* __restrict__ a,
                                                        const float* __restrict__ b,
                                                        const void* __restrict__ adj) {
    int blk = blockIdx.x;
    int tid = threadIdx.x;
    if (blk < 128) {
        // B repack: Wcat[n=o][k=h*256+d] -> fp16
        int o = blk;
        #pragma unroll
        for (int i = 0; i < 2; i++) {
            int q = tid + i * 256;          // 0..511 -> k pair (2q, 2q+1)
            int k = 2 * q;
            int h = k >> 8, d = k & 255;
            float w0 = W[((size_t)h * D_K + d)     * O_DIM + o];
            float w1 = W[((size_t)h * D_K + d + 1) * O_DIM + o];
            __half2 p = __float22half2_rn(make_float2(w0, w1));
            g_WB[o * (KCAT / 2) + q] = *(uint32_t*)&p;
        }
    } else if (blk < 132) {
        // wa[h,d] = sum_o W[h,d,o]*a[h,o]; bbar
        int h = blk - 128;
        int d = tid;
        const float* Wd = W + ((size_t)h * D_K + d) * O_DIM;
        const float* ah = a + h * O_DIM;
        float s = 0.f;
        #pragma unroll 8
        for (int o = 0; o < O_DIM; o++) s += Wd[o] * ah[o];
        g_wa[h * D_K + d] = s;
        if (h == 0 && d < O_DIM)
            g_bbar[d] = 0.25f * (b[d] + b[O_DIM + d] + b[2 * O_DIM + d] + b[3 * O_DIM + d]);
    } else {
        if (tid == 0) {
            const long long* p = (const long long*)adj;
            int ok = 1;
            for (int i = 0; i < 64; i++) {
                long long v = p[i];
                if (v < 0 || v > (long long)V_N) { ok = 0; break; }
            }
            g_adj64 = ok;
        }
    }
}

// ---------------- x prep: fp16 convert + fused attn dots (wa in registers) ----------------
__global__ __launch_bounds__(256) void prepx_kernel(const float* __restrict__ x) {
    int tid  = threadIdx.x;
    int wid  = tid >> 5, lane = tid & 31;
    int d0   = lane * 8;

    float4 wra[NHEAD], wrb[NHEAD];
    #pragma unroll
    for (int h = 0; h < NHEAD; h++) {
        const float* wp = g_wa + h * D_K + d0;
        wra[h] = *(const float4*)wp;
        wrb[h] = *(const float4*)(wp + 4);
    }

    int vbase = blockIdx.x * 16 + wid * 2;
    #pragma unroll
    for (int r = 0; r < 2; r++) {
        int v = vbase + r;
        if (v >= V_N) continue;
        const float* xp = x + (size_t)v * D_K + d0;
        float4 va = *(const float4*)xp;
        float4 vb = *(const float4*)(xp + 4);

        __half2 p0 = __float22half2_rn(make_float2(va.x, va.y));
        __half2 p1 = __float22half2_rn(make_float2(va.z, va.w));
        __half2 p2 = __float22half2_rn(make_float2(vb.x, vb.y));
        __half2 p3 = __float22half2_rn(make_float2(vb.z, vb.w));
        ((uint4*)g_xh)[(size_t)v * 32 + lane] =
            make_uint4(*(uint32_t*)&p0, *(uint32_t*)&p1, *(uint32_t*)&p2, *(uint32_t*)&p3);

        float res[NHEAD];
        #pragma unroll
        for (int h = 0; h < NHEAD; h++) {
            float s = va.x * wra[h].x + va.y * wra[h].y + va.z * wra[h].z + va.w * wra[h].w
                    + vb.x * wrb[h].x + vb.y * wrb[h].y + vb.z * wrb[h].z + vb.w * wrb[h].w;
            #pragma unroll
            for (int off = 16; off; off >>= 1) s += __shfl_xor_sync(0xffffffffu, s, off);
            res[h] = s;
        }
        if (lane == 0)
            *(float4*)(g_attn + (size_t)v * NHEAD) =
                make_float4(res[0], res[1], res[2], res[3]);
    }
}

// ---------------- gather: softmax coefs + x-space aggregation -> Y fp16 ----------------
__global__ __launch_bounds__(256) void gather_kernel(const void* __restrict__ adj) {
    int local = threadIdx.x >> 7;
    int t     = threadIdx.x & 127;
    int v     = blockIdx.x * 2 + local;

    __shared__ float s_coef[2][KNBR * NHEAD];   // [k*4 + h]
    __shared__ int   s_idx [2][KNBR];

    if (t < 64) {
        int k = t & 15;
        int h = t >> 4;
        long long a;
        if (g_adj64) a = ((const long long*)adj)[(size_t)v * KNBR + k];
        else         a = (long long)((const int*)adj)[(size_t)v * KNBR + k];
        bool pad = (a >= (long long)V_N) || (a < 0);
        int n = pad ? 0 : (int)a;
        float sc = pad ? -1e9f : g_attn[(size_t)n * NHEAD + h];

        float mx = sc;
        #pragma unroll
        for (int off = 8; off; off >>= 1)
            mx = fmaxf(mx, __shfl_xor_sync(0xffffffffu, mx, off));
        float e = __expf(sc - mx);
        float sum = e;
        #pragma unroll
        for (int off = 8; off; off >>= 1)
            sum += __shfl_xor_sync(0xffffffffu, sum, off);
        s_coef[local][k * 4 + h] = pad ? 0.f : (e / sum);
        if (h == 0) s_idx[local][k] = n;
    }
    __syncthreads();

    const __half2* xh2 = (const __half2*)g_xh;
    float2 acc[NHEAD];
    #pragma unroll
    for (int h = 0; h < NHEAD; h++) acc[h] = make_float2(0.f, 0.f);

    const float* cf = s_coef[local];
    const int*   ix = s_idx [local];
    #pragma unroll
    for (int k = 0; k < KNBR; k++) {
        int n = ix[k];
        float2 fv = __half22float2(__ldg(xh2 + (size_t)n * 128 + t));
        float4 c4 = *(const float4*)(cf + k * 4);
        acc[0].x = fmaf(c4.x, fv.x, acc[0].x);  acc[0].y = fmaf(c4.x, fv.y, acc[0].y);
        acc[1].x = fmaf(c4.y, fv.x, acc[1].x);  acc[1].y = fmaf(c4.y, fv.y, acc[1].y);
        acc[2].x = fmaf(c4.z, fv.x, acc[2].x);  acc[2].y = fmaf(c4.z, fv.y, acc[2].y);
        acc[3].x = fmaf(c4.w, fv.x, acc[3].x);  acc[3].y = fmaf(c4.w, fv.y, acc[3].y);
    }
    #pragma unroll
    for (int h = 0; h < NHEAD; h++) {
        __half2 p = __float22half2_rn(make_float2(acc[h].x, acc[h].y));
        g_Y[(size_t)v * (KCAT / 2) + h * 128 + t] = *(uint32_t*)&p;
    }
}

// ---------------- GEMM: out = relu(0.25 * Y @ Wcat^T + bbar) ----------------
// [VPAD, 1024] x [1024, 128]; BM=64, BN=128, KC=64; 256 thr (8 warps, 32x32 tiles);
// 3-stage cp.async pipeline, 72 KB smem -> 3 CTA/SM.
#define GM 64
#define GN 128
#define KC 64
#define NCHUNK (KCAT / KC)   // 16
#define NSTAGE 3
#define BUFSZ  24576         // A 8K + B 16K
#define SOA    0
#define SOB    8192
#define SMEM_SZ (NSTAGE * BUFSZ)  // 73728

__device__ __forceinline__ void load_chunk(uint32_t sb, int buf, int kc,
                                           int m0, int tid) {
    uint32_t base = sb + buf * BUFSZ;
    // A: 512 uint4 (64 rows x 8 segs) over 256 threads
    #pragma unroll
    for (int i = 0; i < 2; i++) {
        int idx = tid + i * 256;
        int row = idx >> 3, seg = idx & 7;
        uint32_t sw = SW128((uint32_t)(row * 128 + seg * 16));
        CP_ASYNC16(base + SOA + sw, (const uint4*)g_Y + (size_t)(m0 + row) * 128 + kc * 8 + seg);
    }
    // B: 1024 uint4 (128 rows x 8 segs)
    #pragma unroll
    for (int i = 0; i < 4; i++) {
        int idx = tid + i * 256;
        int n = idx >> 3, seg = idx & 7;
        uint32_t sw = SW128((uint32_t)(n * 128 + seg * 16));
        CP_ASYNC16(base + SOB + sw, (const uint4*)g_WB + (size_t)n * 128 + kc * 8 + seg);
    }
    asm volatile("cp.async.commit_group;" ::: "memory");
}

__global__ __launch_bounds__(256) void gemm_mma_kernel(float* __restrict__ out) {
    extern __shared__ char smem[];
    uint32_t sb = smem_u32(smem);
    int tid = threadIdx.x, wid = tid >> 5, lane = tid & 31;
    int m0 = blockIdx.x * GM;
    int wm = (wid & 1) * 32, wn = (wid >> 1) * 32;   // 2 m-slots x 4 n-slots

    float acc[2][4][4];
    #pragma unroll
    for (int i = 0; i < 2; i++)
        #pragma unroll
        for (int j = 0; j < 4; j++)
            #pragma unroll
            for (int q = 0; q < 4; q++) acc[i][j][q] = 0.f;

    int lrA = lane & 15;
    int hA  = lane >> 4;
    int lrB = (lane & 7) + ((lane >> 4) << 3);
    int hB  = (lane >> 3) & 1;

    load_chunk(sb, 0, 0, m0, tid);
    load_chunk(sb, 1, 1, m0, tid);

    for (int kc = 0; kc < NCHUNK; kc++) {
        if (kc + 2 < NCHUNK) {
            load_chunk(sb, (kc + 2) % NSTAGE, kc + 2, m0, tid);
            asm volatile("cp.async.wait_group 2;" ::: "memory");
        } else {
            asm volatile("cp.async.wait_group 0;" ::: "memory");
        }
        __syncthreads();

        uint32_t base = sb + (kc % NSTAGE) * BUFSZ;
        #pragma unroll
        for (int ks = 0; ks < 4; ks++) {
            uint32_t a_f[2][4];
            #pragma unroll
            for (int mt = 0; mt < 2; mt++) {
                uint32_t off = SW128((uint32_t)((wm + mt * 16 + lrA) * 128 + ks * 32 + hA * 16));
                LDSM4(a_f[mt], base + SOA + off);
            }
            #pragma unroll
            for (int p = 0; p < 2; p++) {
                uint32_t bf[4];
                uint32_t off = SW128((uint32_t)((wn + p * 16 + lrB) * 128 + ks * 32 + hB * 16));
                LDSM4(bf, base + SOB + off);
                #pragma unroll
                for (int mt = 0; mt < 2; mt++) {
                    MMAF16(acc[mt][2 * p],     a_f[mt], &bf[0]);
                    MMAF16(acc[mt][2 * p + 1], a_f[mt], &bf[2]);
                }
            }
        }
        __syncthreads();
    }

    // epilogue: out = relu(0.25*acc + bbar), guarded rows
    int g  = lane >> 2;
    int t2 = (lane & 3) * 2;
    #pragma unroll
    for (int mt = 0; mt < 2; mt++) {
        int r0 = m0 + wm + mt * 16 + g;
        #pragma unroll
        for (int nt = 0; nt < 4; nt++) {
            int c = wn + nt * 8 + t2;
            float bx = g_bbar[c], by = g_bbar[c + 1];
            if (r0 < V_N) {
                float rx = fmaxf(fmaf(acc[mt][nt][0], 0.25f, bx), 0.f);
                float ry = fmaxf(fmaf(acc[mt][nt][1], 0.25f, by), 0.f);
                *(float2*)(out + (size_t)r0 * O_DIM + c) = make_float2(rx, ry);
            }
            if (r0 + 8 < V_N) {
                float rx = fmaxf(fmaf(acc[mt][nt][2], 0.25f, bx), 0.f);
                float ry = fmaxf(fmaf(acc[mt][nt][3], 0.25f, by), 0.f);
                *(float2*)(out + (size_t)(r0 + 8) * O_DIM + c) = make_float2(rx, ry);
            }
        }
    }
}

// ---------------- launch ----------------
extern "C" void kernel_launch(void* const* d_in, const int* in_sizes, int n_in,
                              void* d_out, int out_size) {
    const float* x   = (const float*)d_in[0];   // [V, D]
    const float* W   = (const float*)d_in[1];   // [H, D, O]
    const float* a   = (const float*)d_in[2];   // [H, O]
    const float* b   = (const float*)d_in[3];   // [H, O]
    const void*  adj = d_in[4];                 // [V, K] int32 or int64
    float* out = (float*)d_out;                 // [V, O]

    cudaFuncSetAttribute(gemm_mma_kernel, cudaFuncAttributeMaxDynamicSharedMemorySize, SMEM_SZ);

    prep_misc_kernel<<<133, 256>>>(W, a, b, adj);
    prepx_kernel<<<VPAD / 16, 256>>>(x);
    gather_kernel<<<V_N / 2, 256>>>(adj);
    gemm_mma_kernel<<<VPAD / GM, 256, SMEM_SZ>>>(out);
}